// round 11
// baseline (speedup 1.0000x reference)
#include <cuda_runtime.h>
#include <cstdint>
#include <math.h>

// ---------------- problem constants ----------------
#define NB   16
#define SL   4096
#define DM   64          // d_model
#define DIN  128         // d_inner
#define DST  32          // d_state
#define NH   2           // heads
#define HD   64          // headdim
#define CDIM 192         // d_inner + 2*d_state
#define NPJ  322         // 2*128 + 2*32 + 2
#define MROWS (NB*SL)    // 65536
#define CL   64          // chunk length
#define NC   (SL/CL)     // 64 chunks
#define HSZ  (HD*DST)    // 2048 floats per (b,h,chunk) state

// ---------------- device scratch ----------------
__device__ float  g_z  [(size_t)MROWS * DIN];   // z (gate) only, compact
__device__ float  g_xbc[(size_t)MROWS * CDIM];  // conv+silu activated xBC
__device__ float2 g_dtA[(size_t)MROWS * 2];
__device__ float  g_cd [(size_t)MROWS * 2];     // in-chunk cumulative decay per (row, h)
__device__ float  g_y  [(size_t)MROWS * DIN];   // local scan output
__device__ float  g_buf[2][(size_t)MROWS * DM];
__device__ float  g_hloc[(size_t)NB * NH * NC * HSZ];
__device__ float  g_hin [(size_t)NB * NH * NC * HSZ];

// ---------------- K1: in-proj GEMM + fused conv/SiLU + fused dt ----------------
__global__ __launch_bounds__(128) void k_inproj(const float* __restrict__ xin, int insel,
                                                const float* __restrict__ W,
                                                const float* __restrict__ dt_bias,
                                                const float* __restrict__ A_log,
                                                const float* __restrict__ cw,
                                                const float* __restrict__ cb) {
    __shared__ float pool[12288];                 // 48KB
    float (*Ast)[128] = (float(*)[128])pool;      // [64][128] A transposed
    float (*Bs)[64]   = (float(*)[64])(pool + 8192);
    float (*St)[69]   = (float(*)[69])pool;       // conv staging [131][69]

    const float* in = (insel >= 0) ? g_buf[insel] : xin;
    const int m0 = blockIdx.y * 128;
    const int n0 = blockIdx.x * 64;
    const int tid = threadIdx.x;

    {
        const float4* Arow = (const float4*)(in + (size_t)(m0 + tid) * DM);
#pragma unroll
        for (int q = 0; q < 16; q++) {
            float4 v = Arow[q];
            Ast[q * 4 + 0][tid] = v.x;
            Ast[q * 4 + 1][tid] = v.y;
            Ast[q * 4 + 2][tid] = v.z;
            Ast[q * 4 + 3][tid] = v.w;
        }
    }
#pragma unroll
    for (int i = 0; i < 32; i++) {
        int idx = i * 128 + tid;
        int k = idx >> 6, n = idx & 63;
        int gn = n0 + n;
        Bs[k][n] = (gn < NPJ) ? W[k * NPJ + gn] : 0.f;
    }
    __syncthreads();

    const int tx = tid & 7, ty = tid >> 3;   // 8 x 16
    float acc[8][8];
#pragma unroll
    for (int i = 0; i < 8; i++)
#pragma unroll
        for (int j = 0; j < 8; j++) acc[i][j] = 0.f;

#pragma unroll 8
    for (int k = 0; k < 64; k++) {
        float4 a0 = *(const float4*)&Ast[k][ty * 8 + 0];
        float4 a1 = *(const float4*)&Ast[k][ty * 8 + 4];
        float4 b0 = *(const float4*)&Bs[k][tx * 8 + 0];
        float4 b1 = *(const float4*)&Bs[k][tx * 8 + 4];
        float av[8] = {a0.x, a0.y, a0.z, a0.w, a1.x, a1.y, a1.z, a1.w};
        float bv[8] = {b0.x, b0.y, b0.z, b0.w, b1.x, b1.y, b1.z, b1.w};
#pragma unroll
        for (int i = 0; i < 8; i++)
#pragma unroll
            for (int j = 0; j < 8; j++) acc[i][j] += av[i] * bv[j];
    }

    if (n0 < 128) {
#pragma unroll
        for (int i = 0; i < 8; i++) {
            size_t r = (size_t)(m0 + ty * 8 + i) * DIN + n0 + tx * 8;
            *(float4*)&g_z[r + 0] = make_float4(acc[i][0], acc[i][1], acc[i][2], acc[i][3]);
            *(float4*)&g_z[r + 4] = make_float4(acc[i][4], acc[i][5], acc[i][6], acc[i][7]);
        }
    } else if (n0 >= 320) {
        if (tx == 0) {
            const float A0 = -expf(A_log[0]), A1 = -expf(A_log[1]);
            const float b0v = dt_bias[0], b1v = dt_bias[1];
#pragma unroll
            for (int i = 0; i < 8; i++) {
#pragma unroll
                for (int hh = 0; hh < 2; hh++) {
                    float v = acc[i][hh] + (hh ? b1v : b0v);
                    float dt = (v > 15.f) ? v : log1pf(expf(v));
                    float A = hh ? A1 : A0;
                    g_dtA[(size_t)(m0 + ty * 8 + i) * 2 + hh] = make_float2(dt, expf(dt * A));
                }
            }
        }
    } else {
        __syncthreads();
        const bool first = (m0 & (SL - 1)) == 0;
        for (int j = tid; j < 192; j += 128) {
            int r = j >> 6, n = j & 63;
            float s = 0.f;
            if (!first) {
                const float* arow = in + (size_t)(m0 - 3 + r) * DM;
#pragma unroll 16
                for (int k = 0; k < 64; k++) s += arow[k] * Bs[k][n];
            }
            St[r][n] = s;
        }
        __syncthreads();
#pragma unroll
        for (int i = 0; i < 8; i++)
#pragma unroll
            for (int j = 0; j < 8; j++)
                St[3 + ty * 8 + i][tx * 8 + j] = acc[i][j];
        __syncthreads();

        const int c  = tid & 63;
        const int ch = (n0 - 128) + c;
        const float w0 = cw[ch * 4 + 0], w1 = cw[ch * 4 + 1];
        const float w2 = cw[ch * 4 + 2], w3 = cw[ch * 4 + 3];
        const float bb = cb[ch];
        const int rbase = tid >> 6;
        float* outc = g_xbc + (size_t)m0 * CDIM + ch;
#pragma unroll 8
        for (int r = rbase; r < 128; r += 2) {
            float v = bb + w0 * St[r][c] + w1 * St[r + 1][c]
                         + w2 * St[r + 2][c] + w3 * St[r + 3][c];
            v = v / (1.f + expf(-v));
            outc[(size_t)r * CDIM] = v;
        }
    }
}

// ---------------- K3a: single-pass chunk scan from zero state ----------------
__global__ __launch_bounds__(128) void k_scanA(const float* __restrict__ Dp) {
    __shared__ float Bs[CL][DST];
    __shared__ float Cs[CL][DST];
    const int b = blockIdx.y, c = blockIdx.x;
    const int tid = threadIdx.x, h = tid >> 6, p = tid & 63;
    const size_t row0 = (size_t)b * SL + (size_t)c * CL;

#pragma unroll
    for (int i = 0; i < 16; i++) {
        int idx = i * 128 + tid;
        int t = idx >> 5, n = idx & 31;
        const float* src = &g_xbc[(row0 + t) * CDIM + 128];
        Bs[t][n] = src[n];
        Cs[t][n] = src[32 + n];
    }
    __syncthreads();

    const float*  px = g_xbc + row0 * CDIM + h * HD + p;
    const float2* pd = g_dtA + row0 * 2 + h;
    float*        py = g_y + row0 * DIN + h * HD + p;
    float*        pc = g_cd + row0 * 2 + h;
    const float   dp = Dp[h];

    float hs[DST];
#pragma unroll
    for (int n = 0; n < DST; n++) hs[n] = 0.f;
    float cum = 1.f;

#pragma unroll 2
    for (int t = 0; t < CL; t++) {
        float  xv = px[0];
        float2 da = pd[0];
        float  ru = da.x * xv;
        cum *= da.y;
        float a0 = 0.f, a1 = 0.f, a2 = 0.f, a3 = 0.f;
#pragma unroll
        for (int n = 0; n < DST; n += 4) {
            float4 bv = *(const float4*)&Bs[t][n];
            float4 cv = *(const float4*)&Cs[t][n];
            hs[n + 0] = da.y * hs[n + 0] + ru * bv.x;
            hs[n + 1] = da.y * hs[n + 1] + ru * bv.y;
            hs[n + 2] = da.y * hs[n + 2] + ru * bv.z;
            hs[n + 3] = da.y * hs[n + 3] + ru * bv.w;
            a0 += hs[n + 0] * cv.x;
            a1 += hs[n + 1] * cv.y;
            a2 += hs[n + 2] * cv.z;
            a3 += hs[n + 3] * cv.w;
        }
        py[0] = (a0 + a1) + (a2 + a3) + dp * xv;
        if (p == 0) pc[0] = cum;
        px += CDIM; pd += 2; py += DIN; pc += 2;
    }

    float* out = g_hloc + ((((size_t)(b * NH + h) * NC) + c) * HD + p) * DST;
#pragma unroll
    for (int n = 0; n < DST; n += 4)
        *(float4*)&out[n] = make_float4(hs[n], hs[n + 1], hs[n + 2], hs[n + 3]);
}

// ---------------- K3b: combine chunk states (8-deep prefetch pipeline) ----------------
__global__ __launch_bounds__(256) void k_combine() {
    __shared__ float ds[NC];
    const int bh  = blockIdx.x >> 3;
    const int sub = blockIdx.x & 7;
    const int bb  = bh >> 1, hh = bh & 1;
    if (threadIdx.x < NC)
        ds[threadIdx.x] = g_cd[((size_t)bb * SL + threadIdx.x * CL + CL - 1) * 2 + hh];
    __syncthreads();

    const int off = sub * 256 + threadIdx.x;
    const float* loc = g_hloc + (size_t)bh * NC * HSZ + off;
    float*       hin = g_hin  + (size_t)bh * NC * HSZ + off;

    float H = 0.f;
    float buf[8];
#pragma unroll
    for (int j = 0; j < 8; j++) buf[j] = loc[(size_t)j * HSZ];

#pragma unroll
    for (int cb = 0; cb < NC; cb += 8) {
        float nbuf[8];
        if (cb + 8 < NC) {
#pragma unroll
            for (int j = 0; j < 8; j++) nbuf[j] = loc[(size_t)(cb + 8 + j) * HSZ];
        } else {
#pragma unroll
            for (int j = 0; j < 8; j++) nbuf[j] = 0.f;
        }
#pragma unroll
        for (int j = 0; j < 8; j++) {
            hin[(size_t)(cb + j) * HSZ] = H;
            H = ds[cb + j] * H + buf[j];
        }
#pragma unroll
        for (int j = 0; j < 8; j++) buf[j] = nbuf[j];
    }
}

// ---------------- K4: fused correction + gate*silu + RMSNorm(folded) + out-proj ---------
// One 64-row chunk per block, 256 threads.
// smem layout (floats): Ws[128][64] @0 (nw pre-folded), Yc[64][132] @8192,
//                       Cs[64][32] @16640, cds[64][2] @18688, scale[64] @18816
#define SM_WS   0
#define SM_YC   8192
#define SM_CS   16640
#define SM_CDS  18688
#define SM_SC   18816
#define SM_TOT  18880   // floats -> 75520 bytes

__global__ __launch_bounds__(256) void k_out(const float* __restrict__ nw,
                                             const float* __restrict__ Wout,
                                             float* __restrict__ dout, int outsel) {
    extern __shared__ float sm[];
    float (*Ws)[64]  = (float(*)[64])(sm + SM_WS);
    float (*Yc)[132] = (float(*)[132])(sm + SM_YC);
    float (*Cs)[32]  = (float(*)[32])(sm + SM_CS);
    float (*cds)[2]  = (float(*)[2])(sm + SM_CDS);
    float* scales    = sm + SM_SC;

    float* out = (outsel >= 0) ? g_buf[outsel] : dout;
    const int m0 = blockIdx.x * CL;
    const int b  = m0 >> 12;
    const int c  = (m0 & (SL - 1)) >> 6;
    const int tid = threadIdx.x;

    // Ws tile (128x64, contiguous), multiplied by nw[k]
    {
        float4* Ws4 = (float4*)&Ws[0][0];
        const float4* W4 = (const float4*)Wout;
#pragma unroll
        for (int i = 0; i < 8; i++) {
            int f = i * 256 + tid;          // float4 index; k = f >> 4
            float nwk = __ldg(nw + (f >> 4));
            float4 v = W4[f];
            Ws4[f] = make_float4(v.x * nwk, v.y * nwk, v.z * nwk, v.w * nwk);
        }
    }
    // C rows + cumdecay
#pragma unroll
    for (int i = 0; i < 8; i++) {
        int idx = i * 256 + tid;
        int t = idx >> 5, n = idx & 31;
        Cs[t][n] = g_xbc[(size_t)(m0 + t) * CDIM + 160 + n];
    }
    if (tid < 128) {
        int row = tid >> 1, hh = tid & 1;
        cds[row][hh] = g_cd[(size_t)(m0 + row) * 2 + hh];
    }
    __syncthreads();

    // ---- phase A: correction + gate*silu(z) -> Yc ----
    {
        const int k = tid & 127, rh = tid >> 7;
        const int h = k >> 6, p = k & 63;
        float Hr[DST];
        const float* hin = g_hin + ((((size_t)(b * NH + h) * NC) + c) * HD + p) * DST;
#pragma unroll
        for (int n = 0; n < DST; n += 4) {
            float4 v = *(const float4*)&hin[n];
            Hr[n] = v.x; Hr[n + 1] = v.y; Hr[n + 2] = v.z; Hr[n + 3] = v.w;
        }
        const float* py = g_y + (size_t)(m0 + rh * 32) * DIN + k;
        const float* pz = g_z + (size_t)(m0 + rh * 32) * DIN + k;
#pragma unroll 4
        for (int t = 0; t < 32; t++) {
            int row = rh * 32 + t;
            float a0 = 0.f, a1 = 0.f, a2 = 0.f, a3 = 0.f;
#pragma unroll
            for (int n = 0; n < DST; n += 4) {
                float4 cv = *(const float4*)&Cs[row][n];
                a0 += Hr[n + 0] * cv.x;
                a1 += Hr[n + 1] * cv.y;
                a2 += Hr[n + 2] * cv.z;
                a3 += Hr[n + 3] * cv.w;
            }
            float yv = py[(size_t)t * DIN] + cds[row][h] * ((a0 + a1) + (a2 + a3));
            float zv = pz[(size_t)t * DIN];
            Yc[row][k] = yv * (zv / (1.f + expf(-zv)));
        }
    }
    __syncthreads();

    // ---- phase B: per-row RMS scale only ----
    {
        const int m = tid >> 2, l4 = tid & 3;   // 4 threads per row, 32 cols each
        float ss = 0.f;
#pragma unroll
        for (int q = 0; q < 8; q++) {
            float4 yv = *(const float4*)&Yc[m][l4 * 32 + q * 4];
            ss += yv.x * yv.x + yv.y * yv.y + yv.z * yv.z + yv.w * yv.w;
        }
        ss += __shfl_xor_sync(0xffffffffu, ss, 2);
        ss += __shfl_xor_sync(0xffffffffu, ss, 1);
        if (l4 == 0) scales[m] = rsqrtf(ss * (1.f / 128.f) + 1e-5f);
    }
    __syncthreads();

    // ---- phase C: 64x64 GEMM (K=128), 4x4 micro-tile, scale folded in epilogue ----
    const int tx = tid & 15, ty = tid >> 4;
    float acc[4][4];
#pragma unroll
    for (int i = 0; i < 4; i++)
#pragma unroll
        for (int j = 0; j < 4; j++) acc[i][j] = 0.f;

#pragma unroll 4
    for (int k4 = 0; k4 < 32; k4++) {
        float4 b0 = *(const float4*)&Ws[k4 * 4 + 0][tx * 4];
        float4 b1 = *(const float4*)&Ws[k4 * 4 + 1][tx * 4];
        float4 b2 = *(const float4*)&Ws[k4 * 4 + 2][tx * 4];
        float4 b3 = *(const float4*)&Ws[k4 * 4 + 3][tx * 4];
#pragma unroll
        for (int i = 0; i < 4; i++) {
            float4 a = *(const float4*)&Yc[ty * 4 + i][k4 * 4];
            acc[i][0] += a.x * b0.x + a.y * b1.x + a.z * b2.x + a.w * b3.x;
            acc[i][1] += a.x * b0.y + a.y * b1.y + a.z * b2.y + a.w * b3.y;
            acc[i][2] += a.x * b0.z + a.y * b1.z + a.z * b2.z + a.w * b3.z;
            acc[i][3] += a.x * b0.w + a.y * b1.w + a.z * b2.w + a.w * b3.w;
        }
    }
#pragma unroll
    for (int i = 0; i < 4; i++) {
        float s = scales[ty * 4 + i];
        size_t r = (size_t)(m0 + ty * 4 + i) * DM + tx * 4;
        *(float4*)&out[r] = make_float4(acc[i][0] * s, acc[i][1] * s,
                                        acc[i][2] * s, acc[i][3] * s);
    }
}

// ---------------- launch ----------------
extern "C" void kernel_launch(void* const* d_in, const int* in_sizes, int n_in,
                              void* d_out, int out_size) {
    const float* x       = (const float*)d_in[0];
    const float* Win     = (const float*)d_in[1];
    const float* conv_w  = (const float*)d_in[2];
    const float* conv_b  = (const float*)d_in[3];
    const float* dt_bias = (const float*)d_in[4];
    const float* A_log   = (const float*)d_in[5];
    const float* Dp      = (const float*)d_in[6];
    const float* norm_w  = (const float*)d_in[7];
    const float* Wout    = (const float*)d_in[8];
    float* outp = (float*)d_out;

    cudaFuncSetAttribute(k_out, cudaFuncAttributeMaxDynamicSharedMemorySize,
                         SM_TOT * 4);

    for (int i = 0; i < 8; i++) {
        int insel  = (i == 0) ? -1 : ((i - 1) & 1);
        int outsel = (i == 7) ? -1 : (i & 1);

        k_inproj<<<dim3(6, 512), 128>>>(x, insel, Win + (size_t)i * DM * NPJ,
                                        dt_bias + i * NH, A_log + i * NH,
                                        conv_w + (size_t)i * CDIM * 4,
                                        conv_b + (size_t)i * CDIM);
        k_scanA<<<dim3(NC, NB), 128>>>(Dp + i * NH);
        k_combine<<<NB * NH * 8, 256>>>();
        k_out<<<MROWS / CL, 256, SM_TOT * 4>>>(norm_w + (size_t)i * DIN,
                                               Wout + (size_t)i * DIN * DM,
                                               outp, outsel);
    }
}

// round 12
// speedup vs baseline: 1.5119x; 1.5119x over previous
#include <cuda_runtime.h>
#include <cstdint>
#include <math.h>

// ---------------- problem constants ----------------
#define NB   16
#define SL   4096
#define DM   64          // d_model
#define DIN  128         // d_inner
#define DST  32          // d_state
#define NH   2           // heads
#define HD   64          // headdim
#define CDIM 192         // d_inner + 2*d_state
#define NPJ  322         // 2*128 + 2*32 + 2
#define MROWS (NB*SL)    // 65536
#define CL   64          // chunk length
#define NC   (SL/CL)     // 64 chunks
#define HSZ  (HD*DST)    // 2048 floats per (b,h,chunk) state

// ---------------- device scratch ----------------
__device__ float  g_z  [(size_t)MROWS * DIN];   // z (gate) only, compact
__device__ float  g_xbc[(size_t)MROWS * CDIM];  // conv+silu activated xBC
__device__ float2 g_dtA[(size_t)MROWS * 2];
__device__ float  g_cd [(size_t)MROWS * 2];     // in-chunk cumulative decay per (row, h)
__device__ float  g_y  [(size_t)MROWS * DIN];   // local scan output
__device__ float  g_buf[2][(size_t)MROWS * DM];
__device__ float  g_hloc[(size_t)NB * NH * NC * HSZ];
__device__ float  g_hin [(size_t)NB * NH * NC * HSZ];

// ---------------- K1: in-proj GEMM + fused conv/SiLU + fused dt ----------------
__global__ __launch_bounds__(128) void k_inproj(const float* __restrict__ xin, int insel,
                                                const float* __restrict__ W,
                                                const float* __restrict__ dt_bias,
                                                const float* __restrict__ A_log,
                                                const float* __restrict__ cw,
                                                const float* __restrict__ cb) {
    __shared__ float pool[12288];                 // 48KB
    float (*Ast)[128] = (float(*)[128])pool;      // [64][128] A transposed
    float (*Bs)[64]   = (float(*)[64])(pool + 8192);
    float (*St)[69]   = (float(*)[69])pool;       // conv staging [131][69]

    const float* in = (insel >= 0) ? g_buf[insel] : xin;
    const int m0 = blockIdx.y * 128;
    const int n0 = blockIdx.x * 64;
    const int tid = threadIdx.x;

    {
        const float4* Arow = (const float4*)(in + (size_t)(m0 + tid) * DM);
#pragma unroll
        for (int q = 0; q < 16; q++) {
            float4 v = Arow[q];
            Ast[q * 4 + 0][tid] = v.x;
            Ast[q * 4 + 1][tid] = v.y;
            Ast[q * 4 + 2][tid] = v.z;
            Ast[q * 4 + 3][tid] = v.w;
        }
    }
#pragma unroll
    for (int i = 0; i < 32; i++) {
        int idx = i * 128 + tid;
        int k = idx >> 6, n = idx & 63;
        int gn = n0 + n;
        Bs[k][n] = (gn < NPJ) ? W[k * NPJ + gn] : 0.f;
    }
    __syncthreads();

    const int tx = tid & 7, ty = tid >> 3;   // 8 x 16
    float acc[8][8];
#pragma unroll
    for (int i = 0; i < 8; i++)
#pragma unroll
        for (int j = 0; j < 8; j++) acc[i][j] = 0.f;

#pragma unroll 8
    for (int k = 0; k < 64; k++) {
        float4 a0 = *(const float4*)&Ast[k][ty * 8 + 0];
        float4 a1 = *(const float4*)&Ast[k][ty * 8 + 4];
        float4 b0 = *(const float4*)&Bs[k][tx * 8 + 0];
        float4 b1 = *(const float4*)&Bs[k][tx * 8 + 4];
        float av[8] = {a0.x, a0.y, a0.z, a0.w, a1.x, a1.y, a1.z, a1.w};
        float bv[8] = {b0.x, b0.y, b0.z, b0.w, b1.x, b1.y, b1.z, b1.w};
#pragma unroll
        for (int i = 0; i < 8; i++)
#pragma unroll
            for (int j = 0; j < 8; j++) acc[i][j] += av[i] * bv[j];
    }

    if (n0 < 128) {
#pragma unroll
        for (int i = 0; i < 8; i++) {
            size_t r = (size_t)(m0 + ty * 8 + i) * DIN + n0 + tx * 8;
            *(float4*)&g_z[r + 0] = make_float4(acc[i][0], acc[i][1], acc[i][2], acc[i][3]);
            *(float4*)&g_z[r + 4] = make_float4(acc[i][4], acc[i][5], acc[i][6], acc[i][7]);
        }
    } else if (n0 >= 320) {
        if (tx == 0) {
            const float A0 = -expf(A_log[0]), A1 = -expf(A_log[1]);
            const float b0v = dt_bias[0], b1v = dt_bias[1];
#pragma unroll
            for (int i = 0; i < 8; i++) {
#pragma unroll
                for (int hh = 0; hh < 2; hh++) {
                    float v = acc[i][hh] + (hh ? b1v : b0v);
                    float dt = (v > 15.f) ? v : log1pf(expf(v));
                    float A = hh ? A1 : A0;
                    g_dtA[(size_t)(m0 + ty * 8 + i) * 2 + hh] = make_float2(dt, expf(dt * A));
                }
            }
        }
    } else {
        __syncthreads();
        const bool first = (m0 & (SL - 1)) == 0;
        for (int j = tid; j < 192; j += 128) {
            int r = j >> 6, n = j & 63;
            float s = 0.f;
            if (!first) {
                const float* arow = in + (size_t)(m0 - 3 + r) * DM;
#pragma unroll 16
                for (int k = 0; k < 64; k++) s += arow[k] * Bs[k][n];
            }
            St[r][n] = s;
        }
        __syncthreads();
#pragma unroll
        for (int i = 0; i < 8; i++)
#pragma unroll
            for (int j = 0; j < 8; j++)
                St[3 + ty * 8 + i][tx * 8 + j] = acc[i][j];
        __syncthreads();

        const int c  = tid & 63;
        const int ch = (n0 - 128) + c;
        const float w0 = cw[ch * 4 + 0], w1 = cw[ch * 4 + 1];
        const float w2 = cw[ch * 4 + 2], w3 = cw[ch * 4 + 3];
        const float bb = cb[ch];
        const int rbase = tid >> 6;
        float* outc = g_xbc + (size_t)m0 * CDIM + ch;
#pragma unroll 8
        for (int r = rbase; r < 128; r += 2) {
            float v = bb + w0 * St[r][c] + w1 * St[r + 1][c]
                         + w2 * St[r + 2][c] + w3 * St[r + 3][c];
            v = v / (1.f + expf(-v));
            outc[(size_t)r * CDIM] = v;
        }
    }
}

// ---------------- K3a: single-pass chunk scan from zero state ----------------
__global__ __launch_bounds__(128) void k_scanA(const float* __restrict__ Dp) {
    __shared__ float Bs[CL][DST];
    __shared__ float Cs[CL][DST];
    const int b = blockIdx.y, c = blockIdx.x;
    const int tid = threadIdx.x, h = tid >> 6, p = tid & 63;
    const size_t row0 = (size_t)b * SL + (size_t)c * CL;

#pragma unroll
    for (int i = 0; i < 16; i++) {
        int idx = i * 128 + tid;
        int t = idx >> 5, n = idx & 31;
        const float* src = &g_xbc[(row0 + t) * CDIM + 128];
        Bs[t][n] = src[n];
        Cs[t][n] = src[32 + n];
    }
    __syncthreads();

    const float*  px = g_xbc + row0 * CDIM + h * HD + p;
    const float2* pd = g_dtA + row0 * 2 + h;
    float*        py = g_y + row0 * DIN + h * HD + p;
    float*        pc = g_cd + row0 * 2 + h;
    const float   dp = Dp[h];

    float hs[DST];
#pragma unroll
    for (int n = 0; n < DST; n++) hs[n] = 0.f;
    float cum = 1.f;

#pragma unroll 2
    for (int t = 0; t < CL; t++) {
        float  xv = px[0];
        float2 da = pd[0];
        float  ru = da.x * xv;
        cum *= da.y;
        float a0 = 0.f, a1 = 0.f, a2 = 0.f, a3 = 0.f;
#pragma unroll
        for (int n = 0; n < DST; n += 4) {
            float4 bv = *(const float4*)&Bs[t][n];
            float4 cv = *(const float4*)&Cs[t][n];
            hs[n + 0] = da.y * hs[n + 0] + ru * bv.x;
            hs[n + 1] = da.y * hs[n + 1] + ru * bv.y;
            hs[n + 2] = da.y * hs[n + 2] + ru * bv.z;
            hs[n + 3] = da.y * hs[n + 3] + ru * bv.w;
            a0 += hs[n + 0] * cv.x;
            a1 += hs[n + 1] * cv.y;
            a2 += hs[n + 2] * cv.z;
            a3 += hs[n + 3] * cv.w;
        }
        py[0] = (a0 + a1) + (a2 + a3) + dp * xv;
        if (p == 0) pc[0] = cum;
        px += CDIM; pd += 2; py += DIN; pc += 2;
    }

    float* out = g_hloc + ((((size_t)(b * NH + h) * NC) + c) * HD + p) * DST;
#pragma unroll
    for (int n = 0; n < DST; n += 4)
        *(float4*)&out[n] = make_float4(hs[n], hs[n + 1], hs[n + 2], hs[n + 3]);
}

// ---------------- K3b: combine chunk states (8-deep prefetch pipeline) ----------------
__global__ __launch_bounds__(256) void k_combine() {
    __shared__ float ds[NC];
    const int bh  = blockIdx.x >> 3;
    const int sub = blockIdx.x & 7;
    const int bb  = bh >> 1, hh = bh & 1;
    if (threadIdx.x < NC)
        ds[threadIdx.x] = g_cd[((size_t)bb * SL + threadIdx.x * CL + CL - 1) * 2 + hh];
    __syncthreads();

    const int off = sub * 256 + threadIdx.x;
    const float* loc = g_hloc + (size_t)bh * NC * HSZ + off;
    float*       hin = g_hin  + (size_t)bh * NC * HSZ + off;

    float H = 0.f;
    float buf[8];
#pragma unroll
    for (int j = 0; j < 8; j++) buf[j] = loc[(size_t)j * HSZ];

#pragma unroll
    for (int cb = 0; cb < NC; cb += 8) {
        float nbuf[8];
        if (cb + 8 < NC) {
#pragma unroll
            for (int j = 0; j < 8; j++) nbuf[j] = loc[(size_t)(cb + 8 + j) * HSZ];
        } else {
#pragma unroll
            for (int j = 0; j < 8; j++) nbuf[j] = 0.f;
        }
#pragma unroll
        for (int j = 0; j < 8; j++) {
            hin[(size_t)(cb + j) * HSZ] = H;
            H = ds[cb + j] * H + buf[j];
        }
#pragma unroll
        for (int j = 0; j < 8; j++) buf[j] = nbuf[j];
    }
}

// ---------------- K4: fused correction + gate*silu(z) + RMSNorm + out-proj ----------------
// Round-5 structure; Yc padded [32][132] so phase-C A-reads (4 rows, same col)
// land on distinct banks (132 % 32 == 4) -> conflict-free.
#define YPAD 132
__global__ __launch_bounds__(256) void k_out(const float* __restrict__ nw,
                                             const float* __restrict__ Wout,
                                             float* __restrict__ dout, int outsel) {
    __shared__ float Ws[128][64];     // 32KB
    __shared__ float Yc[32][YPAD];    // 16.5KB
    __shared__ float Cs[32][32];      // 4KB
    __shared__ float cds[32][2];
    float* out = (outsel >= 0) ? g_buf[outsel] : dout;
    const int m0 = blockIdx.x * 32;
    const int b  = m0 >> 12;
    const int c  = (m0 & (SL - 1)) >> 6;
    const int tid = threadIdx.x;

    {
        float4* Ws4 = (float4*)&Ws[0][0];
        const float4* W4 = (const float4*)Wout;
#pragma unroll
        for (int i = 0; i < 8; i++) Ws4[i * 256 + tid] = W4[i * 256 + tid];
    }
    {
        int t = tid >> 3, n = (tid & 7) * 4;
        *(float4*)&Cs[t][n] = *(const float4*)&g_xbc[(size_t)(m0 + t) * CDIM + 160 + n];
        if (tid < 32) {
            cds[tid][0] = g_cd[(size_t)(m0 + tid) * 2 + 0];
            cds[tid][1] = g_cd[(size_t)(m0 + tid) * 2 + 1];
        }
    }
    __syncthreads();

    // phase A: correction y += cumdecay * (C . H_in)
    {
        const int k = tid & 127, rh = tid >> 7;
        const int h = k >> 6, p = k & 63;
        float Hr[DST];
        const float* hin = g_hin + ((((size_t)(b * NH + h) * NC) + c) * HD + p) * DST;
#pragma unroll
        for (int n = 0; n < DST; n += 4) {
            float4 v = *(const float4*)&hin[n];
            Hr[n] = v.x; Hr[n + 1] = v.y; Hr[n + 2] = v.z; Hr[n + 3] = v.w;
        }
        const float* py = g_y + (size_t)(m0 + rh * 16) * DIN + k;
#pragma unroll 4
        for (int t = 0; t < 16; t++) {
            int row = rh * 16 + t;
            float a0 = 0.f, a1 = 0.f, a2 = 0.f, a3 = 0.f;
#pragma unroll
            for (int n = 0; n < DST; n += 4) {
                float4 cv = *(const float4*)&Cs[row][n];
                a0 += Hr[n + 0] * cv.x;
                a1 += Hr[n + 1] * cv.y;
                a2 += Hr[n + 2] * cv.z;
                a3 += Hr[n + 3] * cv.w;
            }
            Yc[row][k] = py[(size_t)t * DIN] + cds[row][h] * ((a0 + a1) + (a2 + a3));
        }
    }
    __syncthreads();

    // phase B: gate * silu(z), RMSNorm (in-place)
    {
        const int m = tid >> 3, l8 = tid & 7;
        const float* zrow = g_z + (size_t)(m0 + m) * DIN + l8 * 16;
        float4 gv[4];
        float ss = 0.f;
#pragma unroll
        for (int q = 0; q < 4; q++) {
            float4 yv = *(const float4*)&Yc[m][l8 * 16 + q * 4];
            float4 zv = *(const float4*)(zrow + q * 4);
            gv[q].x = yv.x * (zv.x / (1.f + expf(-zv.x)));
            gv[q].y = yv.y * (zv.y / (1.f + expf(-zv.y)));
            gv[q].z = yv.z * (zv.z / (1.f + expf(-zv.z)));
            gv[q].w = yv.w * (zv.w / (1.f + expf(-zv.w)));
            ss += gv[q].x * gv[q].x + gv[q].y * gv[q].y + gv[q].z * gv[q].z + gv[q].w * gv[q].w;
        }
        ss += __shfl_xor_sync(0xffffffffu, ss, 4);
        ss += __shfl_xor_sync(0xffffffffu, ss, 2);
        ss += __shfl_xor_sync(0xffffffffu, ss, 1);
        const float scale = rsqrtf(ss * (1.f / 128.f) + 1e-5f);
#pragma unroll
        for (int q = 0; q < 4; q++) {
            int k = l8 * 16 + q * 4;
            float4 nwv = *(const float4*)(nw + k);
            Yc[m][k + 0] = gv[q].x * scale * nwv.x;
            Yc[m][k + 1] = gv[q].y * scale * nwv.y;
            Yc[m][k + 2] = gv[q].z * scale * nwv.z;
            Yc[m][k + 3] = gv[q].w * scale * nwv.w;
        }
    }
    __syncthreads();

    // phase C: 32x64 GEMM, K=128
    const int tx = tid & 15, ty = tid >> 4;
    float acc[2][4];
#pragma unroll
    for (int i = 0; i < 2; i++)
#pragma unroll
        for (int j = 0; j < 4; j++) acc[i][j] = 0.f;

#pragma unroll
    for (int k4 = 0; k4 < 32; k4++) {
        float4 b0 = *(const float4*)&Ws[k4 * 4 + 0][tx * 4];
        float4 b1 = *(const float4*)&Ws[k4 * 4 + 1][tx * 4];
        float4 b2 = *(const float4*)&Ws[k4 * 4 + 2][tx * 4];
        float4 b3 = *(const float4*)&Ws[k4 * 4 + 3][tx * 4];
#pragma unroll
        for (int i = 0; i < 2; i++) {
            float4 a = *(const float4*)&Yc[ty * 2 + i][k4 * 4];
            acc[i][0] += a.x * b0.x + a.y * b1.x + a.z * b2.x + a.w * b3.x;
            acc[i][1] += a.x * b0.y + a.y * b1.y + a.z * b2.y + a.w * b3.y;
            acc[i][2] += a.x * b0.z + a.y * b1.z + a.z * b2.z + a.w * b3.z;
            acc[i][3] += a.x * b0.w + a.y * b1.w + a.z * b2.w + a.w * b3.w;
        }
    }
#pragma unroll
    for (int i = 0; i < 2; i++) {
        size_t r = (size_t)(m0 + ty * 2 + i) * DM + tx * 4;
        *(float4*)&out[r] = make_float4(acc[i][0], acc[i][1], acc[i][2], acc[i][3]);
    }
}

// ---------------- launch ----------------
extern "C" void kernel_launch(void* const* d_in, const int* in_sizes, int n_in,
                              void* d_out, int out_size) {
    const float* x       = (const float*)d_in[0];
    const float* Win     = (const float*)d_in[1];
    const float* conv_w  = (const float*)d_in[2];
    const float* conv_b  = (const float*)d_in[3];
    const float* dt_bias = (const float*)d_in[4];
    const float* A_log   = (const float*)d_in[5];
    const float* Dp      = (const float*)d_in[6];
    const float* norm_w  = (const float*)d_in[7];
    const float* Wout    = (const float*)d_in[8];
    float* outp = (float*)d_out;

    for (int i = 0; i < 8; i++) {
        int insel  = (i == 0) ? -1 : ((i - 1) & 1);
        int outsel = (i == 7) ? -1 : (i & 1);

        k_inproj<<<dim3(6, 512), 128>>>(x, insel, Win + (size_t)i * DM * NPJ,
                                        dt_bias + i * NH, A_log + i * NH,
                                        conv_w + (size_t)i * CDIM * 4,
                                        conv_b + (size_t)i * CDIM);
        k_scanA<<<dim3(NC, NB), 128>>>(Dp + i * NH);
        k_combine<<<NB * NH * 8, 256>>>();
        k_out<<<MROWS / 32, 256>>>(norm_w + (size_t)i * DIN,
                                   Wout + (size_t)i * DIN * DM,
                                   outp, outsel);
    }
}